// round 4
// baseline (speedup 1.0000x reference)
#include <cuda_runtime.h>
#include <cuda_fp16.h>

// Problem constants (from reference setup_inputs)
#define Bn 8
#define Hn 768
#define Wn 768
#define NPIX (Bn * Hn * Wn)          // 4,718,592
#define HWn (Hn * Wn)
#define PROP_TIME 24
#define GROUP 4                       // per-group working set ~66MB, L2-resident

// Fused-tile geometry: output tile 128x32, +5 halo for the intermediate step
#define TX 128
#define TY 32
#define EXTW (TX + 10)                // 138
#define EXTH (TY + 10)                // 42
#define EXTN (EXTW * EXTH)            // 5796
#define R1P 144                       // padded row width for smem r1

// 8 fp16 weights per pixel, one 16B vector load
struct __align__(16) W8 { __half2 h[4]; };

// Scratch: __device__ globals (allocation-free per harness rules).
__device__ W8    g_wh[NPIX];          // ~75.5 MB total, 37.7 MB per group
__device__ float g_base[NPIX];        // ~19 MB
__device__ float g_bufA[NPIX];        // ~19 MB
__device__ float g_bufB[NPIX];        // ~19 MB

// 8-neighbor offsets (dy, dx), reference order
__constant__ int c_dy[8] = {-5, -1, 0, 0, 5, 1,  0,  0};
__constant__ int c_dx[8] = { 0,  0, 5, 1, 0, 0, -5, -1};

// dynamic smem layout
#define SM_R1_BYTES (EXTH * R1P * 4)              // 24192
#define SM_W_BYTES  (TY * TX * 16)                // 65536
#define SM_B_BYTES  (TY * TX * 4)                 // 16384
#define SMEM_BYTES  (SM_R1_BYTES + SM_W_BYTES + SM_B_BYTES)  // 106112

// ---------------------------------------------------------------------------
// Precompute: normalized affinity weights (fp16-rounded), folded base from the
// ROUNDED weights. mask px: w=0, base=raw.  else: base = (1 - sum(w)) * raw.
// ---------------------------------------------------------------------------
__global__ void precompute_kernel(const float* __restrict__ guid,
                                  const float* __restrict__ blur,
                                  const float* __restrict__ sparse)
{
    int i = blockIdx.x * blockDim.x + threadIdx.x;
    if (i >= NPIX) return;

    int x = i % Wn;
    int t = i / Wn;
    int y = t % Hn;
    int b = t / Hn;

    const float* gb = guid + (size_t)b * 8 * HWn;

    float w[8];
    float s = 0.0f;
#pragma unroll
    for (int c = 0; c < 8; ++c) {
        int yy = y + c_dy[c];
        int xx = x + c_dx[c];
        float v = 0.0f;
        if ((unsigned)yy < (unsigned)Hn && (unsigned)xx < (unsigned)Wn)
            v = gb[(size_t)c * HWn + yy * Wn + xx];
        w[c] = v;
        s += fabsf(v);
    }
    float inv = 1.0f / fmaxf(s, 1e-6f);
#pragma unroll
    for (int c = 0; c < 8; ++c) w[c] *= inv;

    float raw  = blur[i];
    bool  mask = sparse[i] > 0.0f;

    if (mask) {
#pragma unroll
        for (int c = 0; c < 8; ++c) w[c] = 0.0f;
    }

    W8 pack;
    float gs = 0.0f;
#pragma unroll
    for (int c = 0; c < 4; ++c) {
        __half2 h = __floats2half2_rn(w[2 * c], w[2 * c + 1]);
        pack.h[c] = h;
        float2 back = __half22float2(h);
        gs += back.x + back.y;
    }

    g_wh[i]   = pack;
    g_base[i] = mask ? raw : (1.0f - gs) * raw;
}

// stencil at (gx,gy) on global field rb, zero padding outside image
__device__ __forceinline__ float apply_taps_global(const float* __restrict__ rb,
                                                   int gx, int gy,
                                                   float2 w01, float2 w23,
                                                   float2 w45, float2 w67,
                                                   float base)
{
    int yw = gy * Wn;
    float up5 = (gy >= 5)       ? __ldg(&rb[yw - 5 * Wn + gx]) : 0.0f;
    float up1 = (gy >= 1)       ? __ldg(&rb[yw - Wn + gx])     : 0.0f;
    float rt5 = (gx + 5 < Wn)   ? __ldg(&rb[yw + gx + 5])      : 0.0f;
    float rt1 = (gx + 1 < Wn)   ? __ldg(&rb[yw + gx + 1])      : 0.0f;
    float dn5 = (gy + 5 < Hn)   ? __ldg(&rb[yw + 5 * Wn + gx]) : 0.0f;
    float dn1 = (gy + 1 < Hn)   ? __ldg(&rb[yw + Wn + gx])     : 0.0f;
    float lf5 = (gx >= 5)       ? __ldg(&rb[yw + gx - 5])      : 0.0f;
    float lf1 = (gx >= 1)       ? __ldg(&rb[yw + gx - 1])      : 0.0f;

    float acc = base;
    acc = fmaf(w01.x, up5, acc);
    acc = fmaf(w01.y, up1, acc);
    acc = fmaf(w23.x, rt5, acc);
    acc = fmaf(w23.y, rt1, acc);
    acc = fmaf(w45.x, dn5, acc);
    acc = fmaf(w45.y, dn1, acc);
    acc = fmaf(w67.x, lf5, acc);
    acc = fmaf(w67.y, lf1, acc);
    return acc;
}

// ---------------------------------------------------------------------------
// Fused double step: rout = Prop(Prop(rin)).
// Stage A: r^{t+1} over ext tile (+5 halo) -> smem; interior w/base cached in smem.
// Stage B: r^{t+2} over interior from smem; only final result written to global.
// ---------------------------------------------------------------------------
__global__ void __launch_bounds__(512, 2) prop2_kernel(const float* __restrict__ rin,
                                                       float* __restrict__ rout,
                                                       int b0)
{
    extern __shared__ char smem[];
    float* r1 = (float*)smem;                                   // [EXTH][R1P]
    W8*    ws = (W8*)(smem + SM_R1_BYTES);                      // [TY*TX]
    float* bs = (float*)(smem + SM_R1_BYTES + SM_W_BYTES);      // [TY*TX]

    int tid = threadIdx.y * 32 + threadIdx.x;
    int X0 = blockIdx.x * TX;
    int Y0 = blockIdx.y * TY;
    int b  = b0 + blockIdx.z;

    const float* rb  = rin + (size_t)b * HWn;
    size_t boff = (size_t)b * HWn;

    // ---- Stage A: compute r^{t+1} over extended tile ----
#pragma unroll 2
    for (int e = tid; e < EXTN; e += 512) {
        int xe = e % EXTW;
        int ye = e / EXTW;
        int gx = X0 - 5 + xe;
        int gy = Y0 - 5 + ye;

        float v = 0.0f;
        if ((unsigned)gx < (unsigned)Wn && (unsigned)gy < (unsigned)Hn) {
            size_t gi = boff + (size_t)gy * Wn + gx;
            uint4 u = __ldcg(reinterpret_cast<const uint4*>(&g_wh[gi]));
            float2 w01 = __half22float2(*reinterpret_cast<__half2*>(&u.x));
            float2 w23 = __half22float2(*reinterpret_cast<__half2*>(&u.y));
            float2 w45 = __half22float2(*reinterpret_cast<__half2*>(&u.z));
            float2 w67 = __half22float2(*reinterpret_cast<__half2*>(&u.w));
            float base = __ldcg(&g_base[gi]);

            v = apply_taps_global(rb, gx, gy, w01, w23, w45, w67, base);

            int ix = xe - 5, iy = ye - 5;
            if ((unsigned)ix < (unsigned)TX && (unsigned)iy < (unsigned)TY) {
                W8 pw; pw.h[0] = *reinterpret_cast<__half2*>(&u.x);
                       pw.h[1] = *reinterpret_cast<__half2*>(&u.y);
                       pw.h[2] = *reinterpret_cast<__half2*>(&u.z);
                       pw.h[3] = *reinterpret_cast<__half2*>(&u.w);
                ws[iy * TX + ix] = pw;
                bs[iy * TX + ix] = base;
            }
        }
        r1[ye * R1P + xe] = v;
    }
    __syncthreads();

    // ---- Stage B: compute r^{t+2} over interior from smem ----
#pragma unroll
    for (int j = 0; j < (TX * TY) / 512; ++j) {
        int p  = tid + j * 512;
        int ix = p % TX;
        int iy = p / TX;
        int xe = ix + 5;          // position in r1
        int ye = iy + 5;

        W8 pw = ws[p];
        float2 w01 = __half22float2(pw.h[0]);
        float2 w23 = __half22float2(pw.h[1]);
        float2 w45 = __half22float2(pw.h[2]);
        float2 w67 = __half22float2(pw.h[3]);
        float base = bs[p];

        const float* rr = &r1[ye * R1P + xe];
        float acc = base;
        acc = fmaf(w01.x, rr[-5 * R1P], acc);
        acc = fmaf(w01.y, rr[-R1P],     acc);
        acc = fmaf(w23.x, rr[5],        acc);
        acc = fmaf(w23.y, rr[1],        acc);
        acc = fmaf(w45.x, rr[5 * R1P],  acc);
        acc = fmaf(w45.y, rr[R1P],      acc);
        acc = fmaf(w67.x, rr[-5],       acc);
        acc = fmaf(w67.y, rr[-1],       acc);

        __stcg(&rout[boff + (size_t)(Y0 + iy) * Wn + (X0 + ix)], acc);
    }
}

// ---------------------------------------------------------------------------
// Launch: precompute once; per 4-batch group run 12 fused double-steps
// back-to-back so that group's fp16 weights stay L2-resident.
// ---------------------------------------------------------------------------
extern "C" void kernel_launch(void* const* d_in, const int* in_sizes, int n_in,
                              void* d_out, int out_size)
{
    const float* guid   = (const float*)d_in[0];   // (B,8,H,W)
    const float* blur   = (const float*)d_in[1];   // (B,1,H,W)
    const float* sparse = (const float*)d_in[2];   // (B,1,H,W)
    float* out = (float*)d_out;                    // (B,1,H,W)

    float *bufA, *bufB;
    cudaGetSymbolAddress((void**)&bufA, g_bufA);
    cudaGetSymbolAddress((void**)&bufB, g_bufB);

    static bool attr_set = false;
    if (!attr_set) {
        cudaFuncSetAttribute(prop2_kernel,
                             cudaFuncAttributeMaxDynamicSharedMemorySize,
                             SMEM_BYTES);
        attr_set = true;
    }

    {
        const int threads = 256;
        const int blocks  = (NPIX + threads - 1) / threads;
        precompute_kernel<<<blocks, threads>>>(guid, blur, sparse);
    }

    dim3 blk(32, 16);
    dim3 grd(Wn / TX, Hn / TY, GROUP);   // 6 x 24 x 4 = 576 blocks

    const int NSTEP = PROP_TIME / 2;     // 12 fused double-steps
    for (int g = 0; g < Bn / GROUP; ++g) {
        int b0 = g * GROUP;
        const float* cur = blur;
        for (int it = 0; it < NSTEP; ++it) {
            float* dst;
            if (it == NSTEP - 1)      dst = out;
            else if ((it & 1) == 0)   dst = bufA;
            else                      dst = bufB;
            prop2_kernel<<<grd, blk, SMEM_BYTES>>>(cur, dst, b0);
            cur = dst;
        }
    }
}

// round 5
// speedup vs baseline: 1.1906x; 1.1906x over previous
#include <cuda_runtime.h>
#include <cuda_fp16.h>

// Problem constants (from reference setup_inputs)
#define Bn 8
#define Hn 768
#define Wn 768
#define NPIX (Bn * Hn * Wn)          // 4,718,592
#define HWn (Hn * Wn)
#define PROP_TIME 24
#define GROUP 4                       // per-group working set L2-resident

// Fused-tile geometry: output tile 64x32, +5 halo for the intermediate step
#define TX 64
#define TY 32
#define EXTW (TX + 10)                // 74
#define EXTH (TY + 10)                // 42
#define R1P 80                        // padded smem row width (floats)

// 8 fp16 weights per pixel, one 16B vector load
struct __align__(16) W8 { __half2 h[4]; };

// Scratch: __device__ globals (allocation-free per harness rules).
__device__ W8    g_wh[NPIX];          // ~75.5 MB total, 37.7 MB per group
__device__ float g_base[NPIX];        // ~19 MB
__device__ float g_bufA[NPIX];        // ~19 MB
__device__ float g_bufB[NPIX];        // ~19 MB

// 8-neighbor offsets (dy, dx), reference order
__constant__ int c_dy[8] = {-5, -1, 0, 0, 5, 1,  0,  0};
__constant__ int c_dx[8] = { 0,  0, 5, 1, 0, 0, -5, -1};

// dynamic smem layout
#define SM_R1_BYTES (EXTH * R1P * 4)               // 13440
#define SM_W_BYTES  (TY * TX * 16)                 // 32768
#define SM_B_BYTES  (TY * TX * 4)                  // 8192
#define SMEM_BYTES  (SM_R1_BYTES + SM_W_BYTES + SM_B_BYTES)  // 54400

// ---------------------------------------------------------------------------
// Precompute: normalized affinity weights (fp16-rounded), folded base from the
// ROUNDED weights. mask px: w=0, base=raw.  else: base = (1 - sum(w)) * raw.
// ---------------------------------------------------------------------------
__global__ void precompute_kernel(const float* __restrict__ guid,
                                  const float* __restrict__ blur,
                                  const float* __restrict__ sparse)
{
    int i = blockIdx.x * blockDim.x + threadIdx.x;
    if (i >= NPIX) return;

    int x = i % Wn;
    int t = i / Wn;
    int y = t % Hn;
    int b = t / Hn;

    const float* gb = guid + (size_t)b * 8 * HWn;

    float w[8];
    float s = 0.0f;
#pragma unroll
    for (int c = 0; c < 8; ++c) {
        int yy = y + c_dy[c];
        int xx = x + c_dx[c];
        float v = 0.0f;
        if ((unsigned)yy < (unsigned)Hn && (unsigned)xx < (unsigned)Wn)
            v = gb[(size_t)c * HWn + yy * Wn + xx];
        w[c] = v;
        s += fabsf(v);
    }
    float inv = 1.0f / fmaxf(s, 1e-6f);
#pragma unroll
    for (int c = 0; c < 8; ++c) w[c] *= inv;

    float raw  = blur[i];
    bool  mask = sparse[i] > 0.0f;

    if (mask) {
#pragma unroll
        for (int c = 0; c < 8; ++c) w[c] = 0.0f;
    }

    W8 pack;
    float gs = 0.0f;
#pragma unroll
    for (int c = 0; c < 4; ++c) {
        __half2 h = __floats2half2_rn(w[2 * c], w[2 * c + 1]);
        pack.h[c] = h;
        float2 back = __half22float2(h);
        gs += back.x + back.y;
    }

    g_wh[i]   = pack;
    g_base[i] = mask ? raw : (1.0f - gs) * raw;
}

// ---------------------------------------------------------------------------
// Fused double step: rout = Prop(Prop(rin)).
// Stage A: r^{t+1} over ext tile (+5 halo) -> smem; interior w/base -> smem.
// Stage B: r^{t+2} over interior from smem; only final result hits global.
// No div/mod: strided 2D loops with compare-only bounds.
// ---------------------------------------------------------------------------
__global__ void __launch_bounds__(512, 3) prop2_kernel(const float* __restrict__ rin,
                                                       float* __restrict__ rout,
                                                       int b0)
{
    extern __shared__ char smem[];
    float* r1 = (float*)smem;                                   // [EXTH][R1P]
    W8*    ws = (W8*)(smem + SM_R1_BYTES);                      // [TY*TX]
    float* bs = (float*)(smem + SM_R1_BYTES + SM_W_BYTES);      // [TY*TX]

    const int tx = threadIdx.x;          // 0..31
    const int ty = threadIdx.y;          // 0..15
    const int tid = ty * 32 + tx;
    const int X0 = blockIdx.x * TX;
    const int Y0 = blockIdx.y * TY;
    const int b  = b0 + blockIdx.z;

    const float* rb = rin + (size_t)b * HWn;
    const size_t boff = (size_t)b * HWn;

    // ---- Stage A: r^{t+1} over extended tile ----
#pragma unroll
    for (int yo = 0; yo < 48; yo += 16) {
        int ye = ty + yo;
        if (ye >= EXTH) break;
        int gy = Y0 - 5 + ye;
        bool yok = (unsigned)gy < (unsigned)Hn;
        int yw = gy * Wn;
#pragma unroll
        for (int xo = 0; xo < 96; xo += 32) {
            int xe = tx + xo;
            if (xe >= EXTW) break;
            int gx = X0 - 5 + xe;

            float v = 0.0f;
            if (yok && (unsigned)gx < (unsigned)Wn) {
                size_t gi = boff + (size_t)yw + gx;
                uint4 u = __ldcg(reinterpret_cast<const uint4*>(&g_wh[gi]));
                float2 w01 = __half22float2(*reinterpret_cast<__half2*>(&u.x));
                float2 w23 = __half22float2(*reinterpret_cast<__half2*>(&u.y));
                float2 w45 = __half22float2(*reinterpret_cast<__half2*>(&u.z));
                float2 w67 = __half22float2(*reinterpret_cast<__half2*>(&u.w));
                float base = __ldcg(&g_base[gi]);

                float up5 = (gy >= 5)     ? __ldg(&rb[yw - 5 * Wn + gx]) : 0.0f;
                float up1 = (gy >= 1)     ? __ldg(&rb[yw - Wn + gx])     : 0.0f;
                float rt5 = (gx + 5 < Wn) ? __ldg(&rb[yw + gx + 5])      : 0.0f;
                float rt1 = (gx + 1 < Wn) ? __ldg(&rb[yw + gx + 1])      : 0.0f;
                float dn5 = (gy + 5 < Hn) ? __ldg(&rb[yw + 5 * Wn + gx]) : 0.0f;
                float dn1 = (gy + 1 < Hn) ? __ldg(&rb[yw + Wn + gx])     : 0.0f;
                float lf5 = (gx >= 5)     ? __ldg(&rb[yw + gx - 5])      : 0.0f;
                float lf1 = (gx >= 1)     ? __ldg(&rb[yw + gx - 1])      : 0.0f;

                float acc = base;
                acc = fmaf(w01.x, up5, acc);
                acc = fmaf(w01.y, up1, acc);
                acc = fmaf(w23.x, rt5, acc);
                acc = fmaf(w23.y, rt1, acc);
                acc = fmaf(w45.x, dn5, acc);
                acc = fmaf(w45.y, dn1, acc);
                acc = fmaf(w67.x, lf5, acc);
                acc = fmaf(w67.y, lf1, acc);
                v = acc;

                int ix = xe - 5, iy = ye - 5;
                if ((unsigned)ix < (unsigned)TX && (unsigned)iy < (unsigned)TY) {
                    W8 pw; pw.h[0] = *reinterpret_cast<__half2*>(&u.x);
                           pw.h[1] = *reinterpret_cast<__half2*>(&u.y);
                           pw.h[2] = *reinterpret_cast<__half2*>(&u.z);
                           pw.h[3] = *reinterpret_cast<__half2*>(&u.w);
                    int ip = iy * TX + ix;
                    ws[ip] = pw;
                    bs[ip] = base;
                }
            }
            r1[ye * R1P + xe] = v;
        }
    }
    __syncthreads();

    // ---- Stage B: r^{t+2} over interior from smem ----
#pragma unroll
    for (int j = 0; j < (TX * TY) / 512; ++j) {
        int p  = tid + j * 512;
        int ix = p & (TX - 1);
        int iy = p >> 6;

        W8 pw = ws[p];
        float2 w01 = __half22float2(pw.h[0]);
        float2 w23 = __half22float2(pw.h[1]);
        float2 w45 = __half22float2(pw.h[2]);
        float2 w67 = __half22float2(pw.h[3]);
        float base = bs[p];

        const float* rr = &r1[(iy + 5) * R1P + (ix + 5)];
        float acc = base;
        acc = fmaf(w01.x, rr[-5 * R1P], acc);
        acc = fmaf(w01.y, rr[-R1P],     acc);
        acc = fmaf(w23.x, rr[5],        acc);
        acc = fmaf(w23.y, rr[1],        acc);
        acc = fmaf(w45.x, rr[5 * R1P],  acc);
        acc = fmaf(w45.y, rr[R1P],      acc);
        acc = fmaf(w67.x, rr[-5],       acc);
        acc = fmaf(w67.y, rr[-1],       acc);

        __stcg(&rout[boff + (size_t)(Y0 + iy) * Wn + (X0 + ix)], acc);
    }
}

// ---------------------------------------------------------------------------
// Launch: precompute once; per 4-batch group run 12 fused double-steps
// back-to-back so that group's fp16 weights stay L2-resident.
// ---------------------------------------------------------------------------
extern "C" void kernel_launch(void* const* d_in, const int* in_sizes, int n_in,
                              void* d_out, int out_size)
{
    const float* guid   = (const float*)d_in[0];   // (B,8,H,W)
    const float* blur   = (const float*)d_in[1];   // (B,1,H,W)
    const float* sparse = (const float*)d_in[2];   // (B,1,H,W)
    float* out = (float*)d_out;                    // (B,1,H,W)

    float *bufA, *bufB;
    cudaGetSymbolAddress((void**)&bufA, g_bufA);
    cudaGetSymbolAddress((void**)&bufB, g_bufB);

    static bool attr_set = false;
    if (!attr_set) {
        cudaFuncSetAttribute(prop2_kernel,
                             cudaFuncAttributeMaxDynamicSharedMemorySize,
                             SMEM_BYTES);
        attr_set = true;
    }

    {
        const int threads = 256;
        const int blocks  = (NPIX + threads - 1) / threads;
        precompute_kernel<<<blocks, threads>>>(guid, blur, sparse);
    }

    dim3 blk(32, 16);
    dim3 grd(Wn / TX, Hn / TY, GROUP);   // 12 x 24 x 4 = 1152 blocks

    const int NSTEP = PROP_TIME / 2;     // 12 fused double-steps
    for (int g = 0; g < Bn / GROUP; ++g) {
        int b0 = g * GROUP;
        const float* cur = blur;
        for (int it = 0; it < NSTEP; ++it) {
            float* dst;
            if (it == NSTEP - 1)      dst = out;
            else if ((it & 1) == 0)   dst = bufA;
            else                      dst = bufB;
            prop2_kernel<<<grd, blk, SMEM_BYTES>>>(cur, dst, b0);
            cur = dst;
        }
    }
}